// round 13
// baseline (speedup 1.0000x reference)
#include <cuda_runtime.h>
#include <cstdint>

// ---------------------------------------------------------------------------
// out[b][j] = (K - Sx[b] - Sm[j] + 2*dot(x[b], m[:,j])) > thr[j]
// One int8 mma.sync GEMM (exact, s32 accum) + row/col sums + fused epilogue.
// tcgen05 is NOT available (harness PTX targets sm_103, not sm_103a).
// ---------------------------------------------------------------------------
#define B_ROWS   2048
#define DIM_IN   4096
#define DIM_OUT  4096

#define TILE_M   128
#define TILE_N   128
#define KCH      64
#define NITER    (DIM_IN / KCH)        // 64
#define PITCH    80                    // 64B data + 16B pad (conflict-free quads)
#define A_STAGE  (TILE_M * PITCH)      // 10240
#define B_STAGE  (TILE_N * PITCH)      // 10240
#define SM_STAGE (A_STAGE + B_STAGE)   // 20480
#define NSTAGE   3
#define SMEM_TOTAL (NSTAGE * SM_STAGE) // 61440

// Scratch (__device__ globals; allocation-free rule)
__device__ __align__(16) uint8_t g_xa[(size_t)B_ROWS * DIM_IN];    // 8MB  A int8 [b][k]
__device__ __align__(16) uint8_t g_mb[(size_t)DIM_OUT * DIM_IN];   // 16MB B int8 [j][k]
__device__ int g_sx[B_ROWS];
__device__ int g_sm[DIM_OUT];

__device__ __forceinline__ uint32_t smem_u32(const void* p) {
    uint32_t a;
    asm("{ .reg .u64 t; cvta.to.shared.u64 t, %1; cvt.u32.u64 %0, t; }" : "=r"(a) : "l"(p));
    return a;
}
__device__ __forceinline__ void cp16(uint32_t dst, const void* src) {
    asm volatile("cp.async.cg.shared.global [%0], [%1], 16;" :: "r"(dst), "l"(src) : "memory");
}
__device__ __forceinline__ void cp_commit() { asm volatile("cp.async.commit_group;" ::: "memory"); }
__device__ __forceinline__ void cp_wait1()  { asm volatile("cp.async.wait_group 1;" ::: "memory"); }

__device__ __forceinline__ void mma_s8(int* c, const uint32_t* a, const uint32_t* b) {
    asm volatile(
        "mma.sync.aligned.m16n8k32.row.col.s32.s8.s8.s32 "
        "{%0,%1,%2,%3}, {%4,%5,%6,%7}, {%8,%9}, {%0,%1,%2,%3};"
        : "+r"(c[0]), "+r"(c[1]), "+r"(c[2]), "+r"(c[3])
        : "r"(a[0]), "r"(a[1]), "r"(a[2]), "r"(a[3]), "r"(b[0]), "r"(b[1]));
}

// ---------------------------------------------------------------------------
// conv_x: int32 0/1 -> int8. 16 values/thread.
// ---------------------------------------------------------------------------
__global__ void conv_x_kernel(const int4* __restrict__ x4) {
    int t = blockIdx.x * blockDim.x + threadIdx.x;      // [0, 2048*256)
    const int4* p = x4 + (size_t)t * 4;
    uint32_t w[4];
#pragma unroll
    for (int i = 0; i < 4; i++) {
        int4 v = p[i];
        w[i] = (uint32_t)v.x | ((uint32_t)v.y << 8) | ((uint32_t)v.z << 16) | ((uint32_t)v.w << 24);
    }
    *reinterpret_cast<uint4*>(g_xa + (size_t)t * 16) = make_uint4(w[0], w[1], w[2], w[3]);
}

// ---------------------------------------------------------------------------
// rowsum: one warp per row of x.
// ---------------------------------------------------------------------------
__global__ void rowsum_kernel(const int4* __restrict__ x4) {
    int warp = (blockIdx.x * blockDim.x + threadIdx.x) >> 5;
    int lane = threadIdx.x & 31;
    const int4* p = x4 + (size_t)warp * 1024;
    int s = 0;
#pragma unroll
    for (int i = 0; i < 32; i++) { int4 v = p[lane + i * 32]; s += v.x + v.y + v.z + v.w; }
#pragma unroll
    for (int o = 16; o; o >>= 1) s += __shfl_xor_sync(0xffffffffu, s, o);
    if (lane == 0) g_sx[warp] = s;
}

__global__ void zero_sm_kernel() {
    g_sm[blockIdx.x * blockDim.x + threadIdx.x] = 0;
}

// ---------------------------------------------------------------------------
// conv_m: masks (4-byte 0/1, [k][j]) -> int8 B [j][k] (transpose) + colsums.
// 64x64 tile per block via smem.
// ---------------------------------------------------------------------------
__global__ __launch_bounds__(256)
void conv_m_kernel(const uint32_t* __restrict__ m) {
    __shared__ uint8_t smt[64][PITCH];     // [j_local][k_local], rows 16B-aligned
    int j0 = blockIdx.x * 64, k0 = blockIdx.y * 64;
    int tid = threadIdx.x;

    // read: k-row r, 16 consecutive j per thread (coalesced 64B)
    {
        int r  = tid >> 2;
        int jq = (tid & 3) * 16;
        const uint32_t* src = m + (size_t)(k0 + r) * DIM_OUT + j0 + jq;
#pragma unroll
        for (int i = 0; i < 16; i++) smt[jq + i][r] = src[i] ? 1 : 0;
    }
    __syncthreads();

    // write: j-row jl, 16-byte k chunk; also colsum contribution
    {
        int jl = tid >> 2;
        int ck = (tid & 3) * 16;
        uint4 v = *reinterpret_cast<const uint4*>(&smt[jl][ck]);
        *reinterpret_cast<uint4*>(g_mb + (size_t)(j0 + jl) * DIM_IN + k0 + ck) = v;
        const uint8_t* b = &smt[jl][ck];
        int s = 0;
#pragma unroll
        for (int i = 0; i < 16; i++) s += b[i];
        atomicAdd(&g_sm[j0 + jl], s);
    }
}

// ---------------------------------------------------------------------------
// GEMM: 128x128 tile, 256 threads (2x4 warps, warp tile 64x32), m16n8k32 s8,
// 3-stage cp.async pipeline, fused threshold epilogue.
// ---------------------------------------------------------------------------
__global__ __launch_bounds__(256, 2)
void gemm_kernel(const int* __restrict__ thr, float* __restrict__ out) {
    extern __shared__ __align__(16) uint8_t smem[];
    const uint32_t sb = smem_u32(smem);

    const int tid    = threadIdx.x;
    const int warp   = tid >> 5;
    const int lane   = tid & 31;
    const int warp_m = warp >> 2;        // 0..1
    const int warp_n = warp & 3;         // 0..3
    const int g      = lane >> 2;        // 0..7
    const int tig    = lane & 3;         // 0..3
    const int row0   = blockIdx.y * TILE_M;
    const int col0   = blockIdx.x * TILE_N;

    const uint8_t* Ag = g_xa + (size_t)row0 * DIM_IN;
    const uint8_t* Bg = g_mb + (size_t)col0 * DIM_IN;

    // chunk copy: 512 A-chunks + 512 B-chunks of 16B, 256 threads -> 2+2 each
    auto copy_stage = [&](int s, int it) {
        uint32_t st = sb + s * SM_STAGE;
#pragma unroll
        for (int c2 = 0; c2 < 2; c2++) {
            int c = tid + c2 * 256;
            int r = c >> 2, kof = (c & 3) * 16;
            cp16(st + r * PITCH + kof, Ag + (size_t)r * DIM_IN + it * KCH + kof);
            cp16(st + A_STAGE + r * PITCH + kof, Bg + (size_t)r * DIM_IN + it * KCH + kof);
        }
        cp_commit();
    };

    copy_stage(0, 0);
    copy_stage(1, 1);

    int acc[4][4][4];
#pragma unroll
    for (int f = 0; f < 4; f++)
#pragma unroll
        for (int h = 0; h < 4; h++)
#pragma unroll
            for (int q = 0; q < 4; q++) acc[f][h][q] = 0;

    for (int it = 0; it < NITER; it++) {
        const int s = it % NSTAGE;
        cp_wait1();
        __syncthreads();
        if (it + 2 < NITER) copy_stage((it + 2) % NSTAGE, it + 2);

        const uint8_t* As = smem + s * SM_STAGE;
        const uint8_t* Bs = smem + s * SM_STAGE + A_STAGE;
#pragma unroll
        for (int ks = 0; ks < 2; ks++) {
            uint32_t a[4][4], b[4][2];
#pragma unroll
            for (int f = 0; f < 4; f++) {
                const uint8_t* p = As + (warp_m * 64 + f * 16 + g) * PITCH + ks * 32 + tig * 4;
                a[f][0] = *reinterpret_cast<const uint32_t*>(p);
                a[f][1] = *reinterpret_cast<const uint32_t*>(p + 8 * PITCH);
                a[f][2] = *reinterpret_cast<const uint32_t*>(p + 16);
                a[f][3] = *reinterpret_cast<const uint32_t*>(p + 8 * PITCH + 16);
            }
#pragma unroll
            for (int h = 0; h < 4; h++) {
                const uint8_t* p = Bs + (warp_n * 32 + h * 8 + g) * PITCH + ks * 32 + tig * 4;
                b[h][0] = *reinterpret_cast<const uint32_t*>(p);
                b[h][1] = *reinterpret_cast<const uint32_t*>(p + 16);
            }
#pragma unroll
            for (int f = 0; f < 4; f++)
#pragma unroll
                for (int h = 0; h < 4; h++) mma_s8(acc[f][h], a[f], b[h]);
        }
        __syncthreads();
    }

    // epilogue: cond = 2*acc - Sx[r] > (thr[j] + Sm[j] - DIM_IN)
    int* cj = reinterpret_cast<int*>(smem);
    for (int i = tid; i < TILE_N; i += 256) {
        int j = col0 + i;
        cj[i] = thr[j] + g_sm[j] - DIM_IN;
    }
    __syncthreads();

#pragma unroll
    for (int f = 0; f < 4; f++) {
        int r0 = row0 + warp_m * 64 + f * 16 + g;
        int sx0 = g_sx[r0], sx1 = g_sx[r0 + 8];
#pragma unroll
        for (int h = 0; h < 4; h++) {
            int jl = warp_n * 32 + h * 8 + 2 * tig;
            int t0 = cj[jl], t1 = cj[jl + 1];
            float2 v0, v1;
            v0.x = (2 * acc[f][h][0] - sx0 > t0) ? 1.0f : 0.0f;
            v0.y = (2 * acc[f][h][1] - sx0 > t1) ? 1.0f : 0.0f;
            v1.x = (2 * acc[f][h][2] - sx1 > t0) ? 1.0f : 0.0f;
            v1.y = (2 * acc[f][h][3] - sx1 > t1) ? 1.0f : 0.0f;
            *reinterpret_cast<float2*>(out + (size_t)r0 * DIM_OUT + col0 + jl) = v0;
            *reinterpret_cast<float2*>(out + (size_t)(r0 + 8) * DIM_OUT + col0 + jl) = v1;
        }
    }
}

// ---------------------------------------------------------------------------
extern "C" void kernel_launch(void* const* d_in, const int* in_sizes, int n_in,
                              void* d_out, int out_size) {
    const int4*     x4   = (const int4*)d_in[0];      // (B, DIM_IN) int32 0/1
    const uint32_t* mask = (const uint32_t*)d_in[1];  // (DIM_IN, DIM_OUT) 4-byte 0/1
    const int*      thr  = (const int*)d_in[2];       // (DIM_OUT,) int32
    float*          out  = (float*)d_out;             // (B, DIM_OUT) float 0/1

    static bool attr_set = false;
    if (!attr_set) {
        cudaFuncSetAttribute(gemm_kernel, cudaFuncAttributeMaxDynamicSharedMemorySize, SMEM_TOTAL);
        attr_set = true;
    }

    conv_x_kernel<<<(B_ROWS * DIM_IN / 16) / 256, 256>>>(x4);
    rowsum_kernel<<<B_ROWS / 8, 256>>>(x4);
    zero_sm_kernel<<<DIM_OUT / 256, 256>>>();
    conv_m_kernel<<<dim3(DIM_OUT / 64, DIM_IN / 64), 256>>>(mask);
    gemm_kernel<<<dim3(DIM_OUT / TILE_N, B_ROWS / TILE_M), 256, SMEM_TOTAL>>>(thr, out);
}

// round 15
// speedup vs baseline: 2.9617x; 2.9617x over previous
#include <cuda_runtime.h>
#include <cstdint>

// Problem constants
#define B_ROWS   2048
#define DIM_IN   4096
#define DIM_OUT  4096
#define KW       128          // DIM_IN / 32 packed words

// Scratch (allocation-free rule: __device__ globals)
__device__ __align__(16) uint32_t g_xp[B_ROWS * KW];     // packed x [b][w]
__device__ __align__(16) uint32_t g_mp[KW * DIM_OUT];    // packed masks, TRANSPOSED [w][j]

__device__ __forceinline__ uint32_t smem_u32(const void* p) {
    uint32_t a;
    asm("{ .reg .u64 t; cvta.to.shared.u64 t, %1; cvt.u32.u64 %0, t; }" : "=r"(a) : "l"(p));
    return a;
}
__device__ __forceinline__ void cp16(uint32_t dst, const void* src) {
    asm volatile("cp.async.cg.shared.global [%0], [%1], 16;" :: "r"(dst), "l"(src) : "memory");
}
__device__ __forceinline__ void cp_commit() { asm volatile("cp.async.commit_group;" ::: "memory"); }
__device__ __forceinline__ void cp_wait1()  { asm volatile("cp.async.wait_group 1;" ::: "memory"); }
__device__ __forceinline__ void cp_wait0()  { asm volatile("cp.async.wait_group 0;" ::: "memory"); }

// ---------------------------------------------------------------------------
// Kernel 1: pack x (int32 0/1) -> bits. One thread per BYTE (8 values).
// ---------------------------------------------------------------------------
__global__ void pack_x_kernel(const int4* __restrict__ x4) {
    int t = blockIdx.x * blockDim.x + threadIdx.x;   // byte index [0, B_ROWS*KW*4)
    const int4* p = x4 + (size_t)t * 2;
    int4 v0 = p[0], v1 = p[1];
    unsigned b = (unsigned)v0.x | ((unsigned)v0.y << 1) | ((unsigned)v0.z << 2) |
                 ((unsigned)v0.w << 3) | ((unsigned)v1.x << 4) | ((unsigned)v1.y << 5) |
                 ((unsigned)v1.z << 6) | ((unsigned)v1.w << 7);
    reinterpret_cast<uint8_t*>(g_xp)[t] = (uint8_t)b;
}

// ---------------------------------------------------------------------------
// Kernel 2: pack masks -> g_mp[w][j]  (TRANSPOSED: coalesced stores).
// masks are 4-byte elements; nonzero == true.
// ---------------------------------------------------------------------------
__global__ void pack_m_kernel(const uint32_t* __restrict__ m) {
    int g = blockIdx.x * blockDim.x + threadIdx.x;   // [0, KW*DIM_OUT)
    int w = g >> 12;            // / DIM_OUT
    int j = g & (DIM_OUT - 1);
    const uint32_t* p = m + (size_t)(w * 32) * DIM_OUT + j;
    unsigned word = 0;
#pragma unroll
    for (int i = 0; i < 32; i++) {
        word |= ((unsigned)(p[(size_t)i * DIM_OUT] != 0u)) << i;
    }
    g_mp[w * DIM_OUT + j] = word;    // coalesced store
}

// ---------------------------------------------------------------------------
// Kernel 3: XNOR-popcount GEMM with CSA compression + cp.async double buffer.
// 8 XOR words -> 4 POPCs (weights 1,2,2,4). Block 64x64, 256 threads, 4x4 tile.
// ---------------------------------------------------------------------------
#define BM 64
#define BN 64
#define CW 16
#define XS_STRIDE (CW + 4)     // 20 words; rows 80B (16B-aligned)
#define MS_STRIDE (BN + 4)     // 68 words; rows 272B (16B-aligned)

__global__ __launch_bounds__(256)
void xnor_gemm_kernel(const int* __restrict__ thr, float* __restrict__ out) {
    __shared__ uint32_t xs[2][BM][XS_STRIDE];   // [buf][row][w]
    __shared__ uint32_t ms[2][CW][MS_STRIDE];   // [buf][w][col]

    const int tid  = threadIdx.x;
    const int tx   = tid & 15;      // 16 col-groups
    const int ty   = tid >> 4;      // 16 row-groups
    const int row0 = blockIdx.y * BM;
    const int col0 = blockIdx.x * BN;

    // cp.async assignment: one 16B chunk each into xs and ms per stage
    const int xr = tid >> 2;            // 0..63
    const int xw = (tid & 3) * 4;       // 0,4,8,12
    const int mw = tid >> 4;            // 0..15
    const int mj = (tid & 15) * 4;      // 0..60

    const uint32_t xs_base0 = smem_u32(&xs[0][xr][xw]);
    const uint32_t xs_base1 = smem_u32(&xs[1][xr][xw]);
    const uint32_t ms_base0 = smem_u32(&ms[0][mw][mj]);
    const uint32_t ms_base1 = smem_u32(&ms[1][mw][mj]);

    auto copy_chunk = [&](int buf, int it) {
        int w0 = it * CW;
        cp16(buf ? xs_base1 : xs_base0, &g_xp[(row0 + xr) * KW + w0 + xw]);
        cp16(buf ? ms_base1 : ms_base0, &g_mp[(w0 + mw) * DIM_OUT + col0 + mj]);
        cp_commit();
    };

    copy_chunk(0, 0);

    int acc[4][4] = {};

    for (int it = 0; it < KW / CW; it++) {
        const int buf = it & 1;
        if (it + 1 < KW / CW) { copy_chunk(buf ^ 1, it + 1); cp_wait1(); }
        else                  { cp_wait0(); }
        __syncthreads();

#pragma unroll
        for (int g = 0; g < CW / 8; g++) {
            uint32_t a[4][8];
            uint32_t b[4][8];
#pragma unroll
            for (int i = 0; i < 4; i++) {
                uint4 v0 = *reinterpret_cast<const uint4*>(&xs[buf][ty * 4 + i][g * 8]);
                uint4 v1 = *reinterpret_cast<const uint4*>(&xs[buf][ty * 4 + i][g * 8 + 4]);
                a[i][0] = v0.x; a[i][1] = v0.y; a[i][2] = v0.z; a[i][3] = v0.w;
                a[i][4] = v1.x; a[i][5] = v1.y; a[i][6] = v1.z; a[i][7] = v1.w;
            }
#pragma unroll
            for (int w = 0; w < 8; w++) {
                uint4 v = *reinterpret_cast<const uint4*>(&ms[buf][g * 8 + w][tx * 4]);
                b[0][w] = v.x; b[1][w] = v.y; b[2][w] = v.z; b[3][w] = v.w;
            }
#pragma unroll
            for (int i = 0; i < 4; i++)
#pragma unroll
                for (int j = 0; j < 4; j++) {
                    uint32_t x0 = a[i][0] ^ b[j][0], x1 = a[i][1] ^ b[j][1];
                    uint32_t x2 = a[i][2] ^ b[j][2], x3 = a[i][3] ^ b[j][3];
                    uint32_t x4 = a[i][4] ^ b[j][4], x5 = a[i][5] ^ b[j][5];
                    uint32_t x6 = a[i][6] ^ b[j][6], x7 = a[i][7] ^ b[j][7];
                    // level 1: two full adders + one half adder (LOP3-friendly)
                    uint32_t s1 = x0 ^ x1 ^ x2, c1 = (x0 & x1) | (x2 & (x0 | x1));
                    uint32_t s2 = x3 ^ x4 ^ x5, c2 = (x3 & x4) | (x5 & (x3 | x4));
                    uint32_t s3 = x6 ^ x7,      c3 = x6 & x7;
                    // level 2
                    uint32_t S  = s1 ^ s2 ^ s3, C  = (s1 & s2) | (s3 & (s1 | s2));
                    uint32_t S2 = c1 ^ c2 ^ c3, C2 = (c1 & c2) | (c3 & (c1 | c2));
                    acc[i][j] += __popc(S) + ((__popc(C) + __popc(S2)) << 1)
                               + (__popc(C2) << 2);
                }
        }
        __syncthreads();
    }

    // Epilogue: matches = DIM_IN - acc; out = matches > thr  <=>  acc < DIM_IN - thr
    const int cbase = col0 + tx * 4;
    int u[4];
#pragma unroll
    for (int j = 0; j < 4; j++) u[j] = DIM_IN - thr[cbase + j];

#pragma unroll
    for (int i = 0; i < 4; i++) {
        int r = row0 + ty * 4 + i;
        float4 v;
        v.x = (acc[i][0] < u[0]) ? 1.0f : 0.0f;
        v.y = (acc[i][1] < u[1]) ? 1.0f : 0.0f;
        v.z = (acc[i][2] < u[2]) ? 1.0f : 0.0f;
        v.w = (acc[i][3] < u[3]) ? 1.0f : 0.0f;
        *reinterpret_cast<float4*>(out + (size_t)r * DIM_OUT + cbase) = v;
    }
}

// ---------------------------------------------------------------------------
extern "C" void kernel_launch(void* const* d_in, const int* in_sizes, int n_in,
                              void* d_out, int out_size) {
    const int4*     x4   = (const int4*)d_in[0];      // (B, DIM_IN) int32 0/1
    const uint32_t* mask = (const uint32_t*)d_in[1];  // (DIM_IN, DIM_OUT) 4-byte 0/1
    const int*      thr  = (const int*)d_in[2];       // (DIM_OUT,) int32
    float*          out  = (float*)d_out;             // (B, DIM_OUT) float 0/1

    // 1) pack x: one thread per byte (8 values)
    pack_x_kernel<<<(B_ROWS * KW * 4) / 256, 256>>>(x4);
    // 2) pack masks (transposed output)
    pack_m_kernel<<<(KW * DIM_OUT) / 256, 256>>>(mask);
    // 3) CSA GEMM + epilogue
    {
        dim3 grid(DIM_OUT / BN, B_ROWS / BM);
        xnor_gemm_kernel<<<grid, 256>>>(thr, out);
    }
}

// round 16
// speedup vs baseline: 3.0044x; 1.0144x over previous
#include <cuda_runtime.h>
#include <cstdint>

// Problem constants
#define B_ROWS   2048
#define DIM_IN   4096
#define DIM_OUT  4096
#define KW       128          // DIM_IN / 32 packed words

// Scratch (allocation-free rule: __device__ globals)
__device__ __align__(16) uint32_t g_xp[B_ROWS * KW];     // packed x [b][w]
__device__ __align__(16) uint32_t g_mp[KW * DIM_OUT];    // packed masks, TRANSPOSED [w][j]

__device__ __forceinline__ uint32_t smem_u32(const void* p) {
    uint32_t a;
    asm("{ .reg .u64 t; cvta.to.shared.u64 t, %1; cvt.u32.u64 %0, t; }" : "=r"(a) : "l"(p));
    return a;
}
__device__ __forceinline__ void cp16(uint32_t dst, const void* src) {
    asm volatile("cp.async.cg.shared.global [%0], [%1], 16;" :: "r"(dst), "l"(src) : "memory");
}
__device__ __forceinline__ void cp_commit() { asm volatile("cp.async.commit_group;" ::: "memory"); }
__device__ __forceinline__ void cp_wait1()  { asm volatile("cp.async.wait_group 1;" ::: "memory"); }
__device__ __forceinline__ void cp_wait0()  { asm volatile("cp.async.wait_group 0;" ::: "memory"); }

// ---------------------------------------------------------------------------
// Fused pack kernel. First PM_BLOCKS blocks pack masks (heavier — scheduled
// first); remaining blocks pack x. Overlaps both DRAM read streams.
// ---------------------------------------------------------------------------
#define PM_THREADS (KW * DIM_OUT / 4)          // 131072 (4 j per thread)
#define PM_BLOCKS  (PM_THREADS / 256)          // 512
#define PX_THREADS (B_ROWS * KW * 4)           // 1048576 (one byte per thread)
#define PX_BLOCKS  (PX_THREADS / 256)          // 4096

__global__ __launch_bounds__(256)
void pack_both_kernel(const int4* __restrict__ x4, const uint32_t* __restrict__ m) {
    if (blockIdx.x < PM_BLOCKS) {
        // ---- pack masks -> g_mp[w][j], 4 columns per thread ----
        int t  = blockIdx.x * 256 + threadIdx.x;   // [0, PM_THREADS)
        int w  = t >> 10;                          // / (DIM_OUT/4)
        int jq = (t & 1023) * 4;
        const uint32_t* p = m + (size_t)(w * 32) * DIM_OUT + jq;
        uint32_t w0 = 0, w1 = 0, w2 = 0, w3 = 0;
#pragma unroll
        for (int i = 0; i < 32; i++) {
            uint4 v = *reinterpret_cast<const uint4*>(p + (size_t)i * DIM_OUT);
            w0 |= ((unsigned)(v.x != 0u)) << i;
            w1 |= ((unsigned)(v.y != 0u)) << i;
            w2 |= ((unsigned)(v.z != 0u)) << i;
            w3 |= ((unsigned)(v.w != 0u)) << i;
        }
        *reinterpret_cast<uint4*>(&g_mp[w * DIM_OUT + jq]) = make_uint4(w0, w1, w2, w3);
    } else {
        // ---- pack x -> g_xp, one byte (8 values) per thread ----
        int t = (blockIdx.x - PM_BLOCKS) * 256 + threadIdx.x;  // byte index
        const int4* p = x4 + (size_t)t * 2;
        int4 v0 = p[0], v1 = p[1];
        unsigned b = (unsigned)v0.x | ((unsigned)v0.y << 1) | ((unsigned)v0.z << 2) |
                     ((unsigned)v0.w << 3) | ((unsigned)v1.x << 4) | ((unsigned)v1.y << 5) |
                     ((unsigned)v1.z << 6) | ((unsigned)v1.w << 7);
        reinterpret_cast<uint8_t*>(g_xp)[t] = (uint8_t)b;
    }
}

// ---------------------------------------------------------------------------
// XNOR-popcount GEMM with CSA compression + cp.async double buffer.
// 8 XOR words -> 4 POPCs (weights 1,2,2,4). Block 64x64, 256 threads, 4x4 tile.
// This loop is AT the alu-pipe floor (~3.0 alu ops per word-pair) — unchanged.
// ---------------------------------------------------------------------------
#define BM 64
#define BN 64
#define CW 16
#define XS_STRIDE (CW + 4)     // 20 words; rows 80B (16B-aligned)
#define MS_STRIDE (BN + 4)     // 68 words; rows 272B (16B-aligned)

__global__ __launch_bounds__(256)
void xnor_gemm_kernel(const int* __restrict__ thr, float* __restrict__ out) {
    __shared__ uint32_t xs[2][BM][XS_STRIDE];   // [buf][row][w]
    __shared__ uint32_t ms[2][CW][MS_STRIDE];   // [buf][w][col]

    const int tid  = threadIdx.x;
    const int tx   = tid & 15;      // 16 col-groups
    const int ty   = tid >> 4;      // 16 row-groups
    const int row0 = blockIdx.y * BM;
    const int col0 = blockIdx.x * BN;

    // cp.async assignment: one 16B chunk each into xs and ms per stage
    const int xr = tid >> 2;            // 0..63
    const int xw = (tid & 3) * 4;       // 0,4,8,12
    const int mw = tid >> 4;            // 0..15
    const int mj = (tid & 15) * 4;      // 0..60

    const uint32_t xs_base0 = smem_u32(&xs[0][xr][xw]);
    const uint32_t xs_base1 = smem_u32(&xs[1][xr][xw]);
    const uint32_t ms_base0 = smem_u32(&ms[0][mw][mj]);
    const uint32_t ms_base1 = smem_u32(&ms[1][mw][mj]);

    auto copy_chunk = [&](int buf, int it) {
        int w0 = it * CW;
        cp16(buf ? xs_base1 : xs_base0, &g_xp[(row0 + xr) * KW + w0 + xw]);
        cp16(buf ? ms_base1 : ms_base0, &g_mp[(w0 + mw) * DIM_OUT + col0 + mj]);
        cp_commit();
    };

    copy_chunk(0, 0);

    int acc[4][4] = {};

    for (int it = 0; it < KW / CW; it++) {
        const int buf = it & 1;
        if (it + 1 < KW / CW) { copy_chunk(buf ^ 1, it + 1); cp_wait1(); }
        else                  { cp_wait0(); }
        __syncthreads();

#pragma unroll
        for (int g = 0; g < CW / 8; g++) {
            uint32_t a[4][8];
            uint32_t b[4][8];
#pragma unroll
            for (int i = 0; i < 4; i++) {
                uint4 v0 = *reinterpret_cast<const uint4*>(&xs[buf][ty * 4 + i][g * 8]);
                uint4 v1 = *reinterpret_cast<const uint4*>(&xs[buf][ty * 4 + i][g * 8 + 4]);
                a[i][0] = v0.x; a[i][1] = v0.y; a[i][2] = v0.z; a[i][3] = v0.w;
                a[i][4] = v1.x; a[i][5] = v1.y; a[i][6] = v1.z; a[i][7] = v1.w;
            }
#pragma unroll
            for (int w = 0; w < 8; w++) {
                uint4 v = *reinterpret_cast<const uint4*>(&ms[buf][g * 8 + w][tx * 4]);
                b[0][w] = v.x; b[1][w] = v.y; b[2][w] = v.z; b[3][w] = v.w;
            }
#pragma unroll
            for (int i = 0; i < 4; i++)
#pragma unroll
                for (int j = 0; j < 4; j++) {
                    uint32_t x0 = a[i][0] ^ b[j][0], x1 = a[i][1] ^ b[j][1];
                    uint32_t x2 = a[i][2] ^ b[j][2], x3 = a[i][3] ^ b[j][3];
                    uint32_t x4 = a[i][4] ^ b[j][4], x5 = a[i][5] ^ b[j][5];
                    uint32_t x6 = a[i][6] ^ b[j][6], x7 = a[i][7] ^ b[j][7];
                    // level 1: two full adders + one half adder (LOP3-friendly)
                    uint32_t s1 = x0 ^ x1 ^ x2, c1 = (x0 & x1) | (x2 & (x0 | x1));
                    uint32_t s2 = x3 ^ x4 ^ x5, c2 = (x3 & x4) | (x5 & (x3 | x4));
                    uint32_t s3 = x6 ^ x7,      c3 = x6 & x7;
                    // level 2
                    uint32_t S  = s1 ^ s2 ^ s3, C  = (s1 & s2) | (s3 & (s1 | s2));
                    uint32_t S2 = c1 ^ c2 ^ c3, C2 = (c1 & c2) | (c3 & (c1 | c2));
                    acc[i][j] += __popc(S) + ((__popc(C) + __popc(S2)) << 1)
                               + (__popc(C2) << 2);
                }
        }
        __syncthreads();
    }

    // Epilogue: matches = DIM_IN - acc; out = matches > thr  <=>  acc < DIM_IN - thr
    const int cbase = col0 + tx * 4;
    int u[4];
#pragma unroll
    for (int j = 0; j < 4; j++) u[j] = DIM_IN - thr[cbase + j];

#pragma unroll
    for (int i = 0; i < 4; i++) {
        int r = row0 + ty * 4 + i;
        float4 v;
        v.x = (acc[i][0] < u[0]) ? 1.0f : 0.0f;
        v.y = (acc[i][1] < u[1]) ? 1.0f : 0.0f;
        v.z = (acc[i][2] < u[2]) ? 1.0f : 0.0f;
        v.w = (acc[i][3] < u[3]) ? 1.0f : 0.0f;
        *reinterpret_cast<float4*>(out + (size_t)r * DIM_OUT + cbase) = v;
    }
}

// ---------------------------------------------------------------------------
extern "C" void kernel_launch(void* const* d_in, const int* in_sizes, int n_in,
                              void* d_out, int out_size) {
    const int4*     x4   = (const int4*)d_in[0];      // (B, DIM_IN) int32 0/1
    const uint32_t* mask = (const uint32_t*)d_in[1];  // (DIM_IN, DIM_OUT) 4-byte 0/1
    const int*      thr  = (const int*)d_in[2];       // (DIM_OUT,) int32
    float*          out  = (float*)d_out;             // (B, DIM_OUT) float 0/1

    // 1) fused pack (masks first, then x)
    pack_both_kernel<<<PM_BLOCKS + PX_BLOCKS, 256>>>(x4, mask);
    // 2) CSA GEMM + epilogue
    {
        dim3 grid(DIM_OUT / BN, B_ROWS / BM);
        xnor_gemm_kernel<<<grid, 256>>>(thr, out);
    }
}